// round 15
// baseline (speedup 1.0000x reference)
#include <cuda_runtime.h>
#include <cuda_fp16.h>
#include <cstdint>
#include <math.h>

#define BATCH 4
#define SEQ   2048
#define DIM   1024

typedef __half h16;

// Scratch (static device allocations; allowed)
__device__ h16  g_xhi[BATCH * SEQ * DIM], g_xlo[BATCH * SEQ * DIM];
__device__ h16  g_Wqhi[DIM * DIM], g_Wqlo[DIM * DIM];
__device__ h16  g_Wkhi[DIM * DIM], g_Wklo[DIM * DIM];
__device__ h16  g_Wvhi[DIM * DIM], g_Wvlo[DIM * DIM];
__device__ h16  g_Qhi[BATCH * SEQ * DIM], g_Qlo[BATCH * SEQ * DIM];
__device__ h16  g_Khi[BATCH * SEQ * DIM], g_Klo[BATCH * SEQ * DIM];
__device__ h16  g_Vhi[BATCH * SEQ * DIM], g_Vlo[BATCH * SEQ * DIM];
__device__ h16  g_VThi[BATCH * SEQ * DIM], g_VTlo[BATCH * SEQ * DIM];
__device__ float g_S[(size_t)BATCH * SEQ * SEQ];
__device__ h16  g_Phi[(size_t)BATCH * SEQ * SEQ], g_Plo[(size_t)BATCH * SEQ * SEQ];

// ---------------------------------------------------------------------------
__device__ __forceinline__ uint32_t smem_u32(const void* p) {
    uint32_t a;
    asm("{ .reg .u64 t; cvta.to.shared.u64 t, %1; cvt.u32.u64 %0, t; }"
        : "=r"(a) : "l"(p));
    return a;
}
__device__ __forceinline__ void cp_async16(uint32_t dst, const void* src) {
    asm volatile("cp.async.cg.shared.global [%0], [%1], 16;"
                 :: "r"(dst), "l"(src) : "memory");
}
#define CP_COMMIT() asm volatile("cp.async.commit_group;" ::: "memory")
#define CP_WAIT(N)  asm volatile("cp.async.wait_group %0;" :: "n"(N) : "memory")

__device__ __forceinline__ void ldsm4(uint32_t& r0, uint32_t& r1, uint32_t& r2,
                                      uint32_t& r3, uint32_t addr) {
    asm volatile("ldmatrix.sync.aligned.m8n8.x4.shared.b16 {%0,%1,%2,%3}, [%4];"
                 : "=r"(r0), "=r"(r1), "=r"(r2), "=r"(r3) : "r"(addr));
}

__device__ __forceinline__ void mma_f16(float* c, const uint32_t* a, const uint32_t* b) {
    asm volatile(
        "mma.sync.aligned.m16n8k16.row.col.f32.f16.f16.f32 "
        "{%0,%1,%2,%3}, {%4,%5,%6,%7}, {%8,%9}, {%0,%1,%2,%3};"
        : "+f"(c[0]), "+f"(c[1]), "+f"(c[2]), "+f"(c[3])
        : "r"(a[0]), "r"(a[1]), "r"(a[2]), "r"(a[3]), "r"(b[0]), "r"(b[1]));
}

__device__ __forceinline__ uint32_t pack_f16(float a, float b) {
    h16 h0 = __float2half_rn(a), h1 = __float2half_rn(b);
    return ((uint32_t)__half_as_ushort(h1) << 16) | __half_as_ushort(h0);
}

// Swizzled smem byte offset within one tile (rows of 64B = 4 chunks of 16B)
__device__ __forceinline__ uint32_t swz(int row, int chunk) {
    return (uint32_t)(row * 64 + ((chunk ^ ((row >> 1) & 3)) << 4));
}

// ---------------------------------------------------------------------------
// fp16 multi-term mma.sync GEMM body, NT form.
// TERMS==3: C = ah*bh + ah*bl + al*bh  (residual ~2^-24)
// TERMS==2: C = ah*bh + al*bh          (A exact, B hi-only; for damped paths)
// CTA 128x128, BK=32, 8 warps (2x4), warp tile 64x32.
// 3-stage cp.async pipeline, prefetch distance 2, one sync per iteration.
// MODE: 0 = fp16 hi/lo output; 1 = fp32 out
// ---------------------------------------------------------------------------
#define BK 32
#define TILE_B 8192
#define STAGE_B (4 * TILE_B)
#define NSTAGE 3
#define SMEM_BYTES (NSTAGE * STAGE_B)  // 98304

template <int MODE, int TERMS>
__device__ __forceinline__ void gemm_body(
    const h16* __restrict__ AhiG, const h16* __restrict__ AloG,
    const h16* __restrict__ BhiG, const h16* __restrict__ BloG,
    float* __restrict__ Cf, h16* __restrict__ ChiG, h16* __restrict__ CloG,
    int lda, int ldb, int ldc,
    long strideA, long strideB, long strideC,
    int kTiles, int bx, int by, int bz)
{
    extern __shared__ char smem[];
    const uint32_t sbase = smem_u32(smem);
    const int tid = threadIdx.x;
    const int wid = tid >> 5;
    const int lid = tid & 31;
    const int warp_m = wid >> 2;
    const int warp_n = wid & 3;
    const int g  = lid >> 2;
    const int t4 = lid & 3;

    const long aoff = (long)bz * strideA + (long)by * 128 * lda;
    const long boff = (long)bz * strideB + (long)bx * 128 * ldb;
    const h16* Ahi = AhiG + aoff;
    const h16* Alo = AloG + aoff;
    const h16* Bhi = BhiG + boff;
    const h16* Blo = (TERMS == 3) ? (BloG + boff) : nullptr;

    auto tbase = [&](int s, int o) { return sbase + (uint32_t)(s * STAGE_B + o * TILE_B); };

    auto load_op = [&](const h16* G, int ld, uint32_t dst, int kt) {
        const h16* src = G + kt * BK;
        #pragma unroll
        for (int i = 0; i < 2; i++) {
            int id  = i * 256 + tid;
            int row = id >> 2;
            int c   = id & 3;
            cp_async16(dst + swz(row, c), src + (long)row * ld + c * 8);
        }
    };
    auto load_stage = [&](int s, int kt) {
        load_op(Ahi, lda, tbase(s, 0), kt);
        load_op(Alo, lda, tbase(s, 1), kt);
        load_op(Bhi, ldb, tbase(s, 2), kt);
        if (TERMS == 3) load_op(Blo, ldb, tbase(s, 3), kt);
    };

    float acc[4][4][4];
    #pragma unroll
    for (int i = 0; i < 4; i++)
        #pragma unroll
        for (int j = 0; j < 4; j++)
            #pragma unroll
            for (int r = 0; r < 4; r++) acc[i][j][r] = 0.0f;

    const int mat = lid >> 3;
    const int mrw = lid & 7;
    const int a_roff = (mat & 1) * 8 + mrw;
    const int a_coff = mat >> 1;
    const int b_roff = (mat >> 1) * 8 + mrw;
    const int b_coff = mat & 1;

    load_stage(0, 0);
    CP_COMMIT();
    load_stage(1, 1);   // kTiles >= 4 always
    CP_COMMIT();

    int buf = 0;
    for (int kt = 0; kt < kTiles; kt++) {
        if (kt + 1 < kTiles) { CP_WAIT(1); } else { CP_WAIT(0); }
        __syncthreads();

        const uint32_t tAhi = tbase(buf, 0), tAlo = tbase(buf, 1);
        const uint32_t tBhi = tbase(buf, 2), tBlo = tbase(buf, 3);

        #pragma unroll
        for (int kk = 0; kk < 2; kk++) {
            uint32_t bh[4][2], bl[4][2];
            #pragma unroll
            for (int p = 0; p < 2; p++) {
                const int nb = warp_n * 32 + p * 16 + b_roff;
                const uint32_t off = swz(nb, kk * 2 + b_coff);
                ldsm4(bh[2*p][0], bh[2*p][1], bh[2*p+1][0], bh[2*p+1][1], tBhi + off);
                if (TERMS == 3)
                    ldsm4(bl[2*p][0], bl[2*p][1], bl[2*p+1][0], bl[2*p+1][1], tBlo + off);
            }
            #pragma unroll
            for (int mt = 0; mt < 4; mt++) {
                const int rb = warp_m * 64 + mt * 16 + a_roff;
                const uint32_t off = swz(rb, kk * 2 + a_coff);
                uint32_t ah[4], al[4];
                ldsm4(ah[0], ah[1], ah[2], ah[3], tAhi + off);
                ldsm4(al[0], al[1], al[2], al[3], tAlo + off);
                #pragma unroll
                for (int nt = 0; nt < 4; nt++) {
                    mma_f16(acc[mt][nt], ah, bh[nt]);
                    if (TERMS == 3) mma_f16(acc[mt][nt], ah, bl[nt]);
                    mma_f16(acc[mt][nt], al, bh[nt]);
                }
            }
        }

        if (kt + 2 < kTiles) {
            int nb = buf + 2; if (nb >= NSTAGE) nb -= NSTAGE;
            load_stage(nb, kt + 2);
            CP_COMMIT();
        }
        if (++buf == NSTAGE) buf = 0;
    }

    const long coff = (long)bz * strideC + (long)by * 128 * ldc + (long)bx * 128;
    #pragma unroll
    for (int mt = 0; mt < 4; mt++) {
        const int r0 = warp_m * 64 + mt * 16 + g;
        #pragma unroll
        for (int nt = 0; nt < 4; nt++) {
            const int c0 = warp_n * 32 + nt * 8 + 2 * t4;
            float v0 = acc[mt][nt][0], v1 = acc[mt][nt][1];
            float v2 = acc[mt][nt][2], v3 = acc[mt][nt][3];
            if (MODE == 0) {
                h16* Chi = ChiG + coff;
                h16* Clo = CloG + coff;
                uint32_t h01 = pack_f16(v0, v1);
                uint32_t h23 = pack_f16(v2, v3);
                *(uint32_t*)(Chi + (long)r0 * ldc + c0) = h01;
                *(uint32_t*)(Chi + (long)(r0 + 8) * ldc + c0) = h23;
                h16 h0 = __ushort_as_half((uint16_t)(h01 & 0xffff));
                h16 h1 = __ushort_as_half((uint16_t)(h01 >> 16));
                h16 h2 = __ushort_as_half((uint16_t)(h23 & 0xffff));
                h16 h3 = __ushort_as_half((uint16_t)(h23 >> 16));
                *(uint32_t*)(Clo + (long)r0 * ldc + c0) =
                    pack_f16(v0 - __half2float(h0), v1 - __half2float(h1));
                *(uint32_t*)(Clo + (long)(r0 + 8) * ldc + c0) =
                    pack_f16(v2 - __half2float(h2), v3 - __half2float(h3));
            } else {
                float* C = Cf + coff;
                *(float2*)(C + (long)r0 * ldc + c0) = make_float2(v0, v1);
                *(float2*)(C + (long)(r0 + 8) * ldc + c0) = make_float2(v2, v3);
            }
        }
    }
}

// ---------------------------------------------------------------------------
// Fused QKV projection: grid (DIM/128, BS/128, 3); z selects weight/output.
// z=0,1 (Q,K): 2-term (softmax-damped path). z=2 (V): 3-term (direct path).
// ---------------------------------------------------------------------------
struct QKVParams {
    const h16* bh[3]; const h16* bl[3];
    h16* ch[3]; h16* cl[3];
};

__global__ __launch_bounds__(256, 2) void mma_qkv(
    const h16* __restrict__ xhi, const h16* __restrict__ xlo, QKVParams p)
{
    const int z = blockIdx.z;
    if (z < 2)
        gemm_body<0, 2>(xhi, xlo, p.bh[z], p.bl[z], nullptr, p.ch[z], p.cl[z],
                        DIM, DIM, DIM, 0, 0, 0, DIM / BK,
                        blockIdx.x, blockIdx.y, 0);
    else
        gemm_body<0, 3>(xhi, xlo, p.bh[z], p.bl[z], nullptr, p.ch[z], p.cl[z],
                        DIM, DIM, DIM, 0, 0, 0, DIM / BK,
                        blockIdx.x, blockIdx.y, 0);
}

// ---------------------------------------------------------------------------
// Scores: compact triangular grid (136 blocks per batch), 3-term.
// ---------------------------------------------------------------------------
__global__ __launch_bounds__(256, 2) void mma_scores(
    const h16* __restrict__ Qhi, const h16* __restrict__ Qlo,
    const h16* __restrict__ Khi, const h16* __restrict__ Klo,
    float* __restrict__ S)
{
    const int idx = blockIdx.x;
    int by = (int)((__fsqrt_rn(8.0f * idx + 1.0f) - 1.0f) * 0.5f);
    if ((by + 1) * (by + 2) / 2 <= idx) by++;
    if (by * (by + 1) / 2 > idx) by--;
    const int bx = idx - by * (by + 1) / 2;
    gemm_body<1, 3>(Qhi, Qlo, Khi, Klo, S, nullptr, nullptr,
                    DIM, DIM, SEQ,
                    (long)SEQ * DIM, (long)SEQ * DIM, (long)SEQ * SEQ,
                    DIM / BK, bx, by, blockIdx.y);
}

// ---------------------------------------------------------------------------
// PV: heavy-first scheduling (by reversed), causal k-limit, 3-term.
// ---------------------------------------------------------------------------
__global__ __launch_bounds__(256, 2) void mma_pv(
    const h16* __restrict__ Phi, const h16* __restrict__ Plo,
    const h16* __restrict__ VThi, const h16* __restrict__ VTlo,
    float* __restrict__ out)
{
    const int by = (int)gridDim.y - 1 - (int)blockIdx.y;   // heavy CTAs first
    gemm_body<1, 3>(Phi, Plo, VThi, VTlo, out, nullptr, nullptr,
                    SEQ, SEQ, DIM,
                    (long)SEQ * SEQ, (long)SEQ * DIM, (long)SEQ * DIM,
                    (by + 1) * 4, blockIdx.x, by, blockIdx.z);
}

// ---------------------------------------------------------------------------
// Fused split: x + Wq + Wk + Wv in one launch (fp32 -> fp16 hi/lo).
// ---------------------------------------------------------------------------
#define NX (BATCH * SEQ * DIM)
#define NW (DIM * DIM)

struct SplitParams {
    const float* src[4];
    h16* hi[4]; h16* lo[4];
    int n[4];
};

__global__ __launch_bounds__(256) void split_all_kernel(SplitParams p)
{
    int i = blockIdx.x * 256 + threadIdx.x;
    #pragma unroll
    for (int s = 0; s < 4; s++) {
        int j = i;
        if (j < p.n[s]) {
            float v = p.src[s][j];
            h16 h = __float2half_rn(v);
            p.hi[s][j] = h;
            p.lo[s][j] = __float2half_rn(v - __half2float(h));
        }
        i -= p.n[s];
        if (i < 0) return;
    }
}

// ---------------------------------------------------------------------------
// fp16 hi/lo transpose: per batch [S, D] -> [D, S]
// ---------------------------------------------------------------------------
__global__ __launch_bounds__(256) void transpose_h16_kernel(
    const h16* __restrict__ hi, const h16* __restrict__ lo,
    h16* __restrict__ thi, h16* __restrict__ tlo)
{
    __shared__ h16 th[32][34], tl[32][34];
    const int b = blockIdx.z;
    const int s0 = blockIdx.x * 32, d0 = blockIdx.y * 32;
    const h16* srch = hi + (long)b * SEQ * DIM;
    const h16* srcl = lo + (long)b * SEQ * DIM;
    h16* dsth = thi + (long)b * SEQ * DIM;
    h16* dstl = tlo + (long)b * SEQ * DIM;
    const int x = threadIdx.x, y = threadIdx.y;
    #pragma unroll
    for (int i = 0; i < 32; i += 8) {
        long o = (long)(s0 + y + i) * DIM + d0 + x;
        th[y + i][x] = srch[o];
        tl[y + i][x] = srcl[o];
    }
    __syncthreads();
    #pragma unroll
    for (int i = 0; i < 32; i += 8) {
        long o = (long)(d0 + y + i) * SEQ + s0 + x;
        dsth[o] = th[x][y + i];
        dstl[o] = tl[x][y + i];
    }
}

// ---------------------------------------------------------------------------
// Causal row softmax, single pass: row held in registers (<=8 elems/thread).
// ---------------------------------------------------------------------------
__global__ __launch_bounds__(256) void softmax_kernel(
    const float* __restrict__ S, h16* __restrict__ Phi, h16* __restrict__ Plo)
{
    const int q = blockIdx.x;
    const int b = blockIdx.y;
    const float* row = S + (long)b * SEQ * SEQ + (long)q * SEQ;
    h16* ph = Phi + (long)b * SEQ * SEQ + (long)q * SEQ;
    h16* pl = Plo + (long)b * SEQ * SEQ + (long)q * SEQ;
    const int klen = q + 1;
    const int kpad = ((q >> 7) + 1) << 7;
    const int tid = threadIdx.x;
    const float scale = 0.03125f;   // 1/sqrt(1024)

    __shared__ float red[8];

    float v[8];
    float m = -1e30f;
    #pragma unroll
    for (int i = 0; i < 8; i++) {
        int j = tid + i * 256;
        v[i] = (j < klen) ? row[j] * scale : -1e30f;
        m = fmaxf(m, v[i]);
    }
    #pragma unroll
    for (int o = 16; o > 0; o >>= 1) m = fmaxf(m, __shfl_xor_sync(0xffffffffu, m, o));
    if ((tid & 31) == 0) red[tid >> 5] = m;
    __syncthreads();
    if (tid < 32) {
        float t = (tid < 8) ? red[tid] : -1e30f;
        #pragma unroll
        for (int o = 4; o > 0; o >>= 1) t = fmaxf(t, __shfl_xor_sync(0xffffffffu, t, o));
        if (tid == 0) red[0] = t;
    }
    __syncthreads();
    m = red[0];
    __syncthreads();

    float s = 0.0f;
    #pragma unroll
    for (int i = 0; i < 8; i++) {
        v[i] = __expf(v[i] - m);
        s += v[i];
    }
    #pragma unroll
    for (int o = 16; o > 0; o >>= 1) s += __shfl_xor_sync(0xffffffffu, s, o);
    if ((tid & 31) == 0) red[tid >> 5] = s;
    __syncthreads();
    if (tid < 32) {
        float t = (tid < 8) ? red[tid] : 0.0f;
        #pragma unroll
        for (int o = 4; o > 0; o >>= 1) t += __shfl_xor_sync(0xffffffffu, t, o);
        if (tid == 0) red[0] = t;
    }
    __syncthreads();
    const float inv = 1.0f / red[0];

    #pragma unroll
    for (int i = 0; i < 8; i++) {
        int j = tid + i * 256;
        if (j < klen) {
            float p = v[i] * inv;
            h16 h = __float2half_rn(p);
            ph[j] = h;
            pl[j] = __float2half_rn(p - __half2float(h));
        } else if (j < kpad) {
            ph[j] = __ushort_as_half(0);
            pl[j] = __ushort_as_half(0);
        }
    }
}

// ---------------------------------------------------------------------------
extern "C" void kernel_launch(void* const* d_in, const int* in_sizes, int n_in,
                              void* d_out, int out_size)
{
    const float* x  = (const float*)d_in[0];
    const float* Wq = (const float*)d_in[1];
    const float* Wk = (const float*)d_in[2];
    const float* Wv = (const float*)d_in[3];
    float* out = (float*)d_out;

    h16 *xhi, *xlo, *Wqhi, *Wqlo, *Wkhi, *Wklo, *Wvhi, *Wvlo;
    h16 *Qhi, *Qlo, *Khi, *Klo, *Vhi, *Vlo, *VThi, *VTlo, *Phi, *Plo;
    float *S;
    cudaGetSymbolAddress((void**)&xhi,  g_xhi);  cudaGetSymbolAddress((void**)&xlo,  g_xlo);
    cudaGetSymbolAddress((void**)&Wqhi, g_Wqhi); cudaGetSymbolAddress((void**)&Wqlo, g_Wqlo);
    cudaGetSymbolAddress((void**)&Wkhi, g_Wkhi); cudaGetSymbolAddress((void**)&Wklo, g_Wklo);
    cudaGetSymbolAddress((void**)&Wvhi, g_Wvhi); cudaGetSymbolAddress((void**)&Wvlo, g_Wvlo);
    cudaGetSymbolAddress((void**)&Qhi,  g_Qhi);  cudaGetSymbolAddress((void**)&Qlo,  g_Qlo);
    cudaGetSymbolAddress((void**)&Khi,  g_Khi);  cudaGetSymbolAddress((void**)&Klo,  g_Klo);
    cudaGetSymbolAddress((void**)&Vhi,  g_Vhi);  cudaGetSymbolAddress((void**)&Vlo,  g_Vlo);
    cudaGetSymbolAddress((void**)&VThi, g_VThi); cudaGetSymbolAddress((void**)&VTlo, g_VTlo);
    cudaGetSymbolAddress((void**)&S,    g_S);
    cudaGetSymbolAddress((void**)&Phi,  g_Phi);  cudaGetSymbolAddress((void**)&Plo,  g_Plo);

    cudaFuncSetAttribute(mma_qkv,    cudaFuncAttributeMaxDynamicSharedMemorySize, SMEM_BYTES);
    cudaFuncSetAttribute(mma_scores, cudaFuncAttributeMaxDynamicSharedMemorySize, SMEM_BYTES);
    cudaFuncSetAttribute(mma_pv,     cudaFuncAttributeMaxDynamicSharedMemorySize, SMEM_BYTES);

    // 0) fused splits (x, Wq, Wk, Wv) -> fp16 hi/lo
    {
        SplitParams sp;
        sp.src[0] = x;  sp.hi[0] = xhi;  sp.lo[0] = xlo;  sp.n[0] = NX;
        sp.src[1] = Wq; sp.hi[1] = Wqhi; sp.lo[1] = Wqlo; sp.n[1] = NW;
        sp.src[2] = Wk; sp.hi[2] = Wkhi; sp.lo[2] = Wklo; sp.n[2] = NW;
        sp.src[3] = Wv; sp.hi[3] = Wvhi; sp.lo[3] = Wvlo; sp.n[3] = NW;
        int total = NX + 3 * NW;
        split_all_kernel<<<(total + 255) / 256, 256>>>(sp);
    }

    // 1) fused QKV projections (Q,K 2-term; V 3-term)
    {
        QKVParams p;
        p.bh[0] = Wqhi; p.bl[0] = Wqlo; p.ch[0] = Qhi; p.cl[0] = Qlo;
        p.bh[1] = Wkhi; p.bl[1] = Wklo; p.ch[1] = Khi; p.cl[1] = Klo;
        p.bh[2] = Wvhi; p.bl[2] = Wvlo; p.ch[2] = Vhi; p.cl[2] = Vlo;
        dim3 grid(DIM / 128, (BATCH * SEQ) / 128, 3);
        mma_qkv<<<grid, 256, SMEM_BYTES>>>(xhi, xlo, p);
    }

    // 2) V transpose (fp16 permutation)
    {
        dim3 grid(SEQ / 32, DIM / 32, BATCH);
        transpose_h16_kernel<<<grid, dim3(32, 8)>>>(Vhi, Vlo, VThi, VTlo);
    }

    // 3) scores: compact triangular grid (136 blocks x 4 batches)
    {
        dim3 grid(136, BATCH);
        mma_scores<<<grid, 256, SMEM_BYTES>>>(Qhi, Qlo, Khi, Klo, S);
    }

    // 4) softmax -> P hi/lo
    {
        dim3 grid(SEQ, BATCH);
        softmax_kernel<<<grid, 256>>>(S, Phi, Plo);
    }

    // 5) O = P @ VT^T, heavy-first scheduling
    {
        dim3 grid(DIM / 128, SEQ / 128, BATCH);
        mma_pv<<<grid, 256, SMEM_BYTES>>>(Phi, Plo, VThi, VTlo, out);
    }
}

// round 16
// speedup vs baseline: 1.3864x; 1.3864x over previous
#include <cuda_runtime.h>
#include <cuda_bf16.h>
#include <cstdint>
#include <math.h>

#define BATCH 4
#define SEQ   2048
#define DIM   1024

typedef __nv_bfloat16 bf16;

// Scratch (static device allocations; allowed)
__device__ bf16  g_xhi[BATCH * SEQ * DIM], g_xlo[BATCH * SEQ * DIM];
__device__ bf16  g_Wqhi[DIM * DIM], g_Wqlo[DIM * DIM];
__device__ bf16  g_Wkhi[DIM * DIM], g_Wklo[DIM * DIM];
__device__ bf16  g_Wvhi[DIM * DIM], g_Wvlo[DIM * DIM];
__device__ bf16  g_Qhi[BATCH * SEQ * DIM], g_Qlo[BATCH * SEQ * DIM];
__device__ bf16  g_Khi[BATCH * SEQ * DIM], g_Klo[BATCH * SEQ * DIM];
__device__ bf16  g_Vhi[BATCH * SEQ * DIM], g_Vlo[BATCH * SEQ * DIM];
__device__ bf16  g_VThi[BATCH * SEQ * DIM], g_VTlo[BATCH * SEQ * DIM];
__device__ float g_S[(size_t)BATCH * SEQ * SEQ];
__device__ bf16  g_Phi[(size_t)BATCH * SEQ * SEQ], g_Plo[(size_t)BATCH * SEQ * SEQ];

// ---------------------------------------------------------------------------
__device__ __forceinline__ uint32_t smem_u32(const void* p) {
    uint32_t a;
    asm("{ .reg .u64 t; cvta.to.shared.u64 t, %1; cvt.u32.u64 %0, t; }"
        : "=r"(a) : "l"(p));
    return a;
}
__device__ __forceinline__ void cp_async16(uint32_t dst, const void* src) {
    asm volatile("cp.async.cg.shared.global [%0], [%1], 16;"
                 :: "r"(dst), "l"(src) : "memory");
}
#define CP_COMMIT() asm volatile("cp.async.commit_group;" ::: "memory")
#define CP_WAIT(N)  asm volatile("cp.async.wait_group %0;" :: "n"(N) : "memory")

__device__ __forceinline__ void ldsm4(uint32_t& r0, uint32_t& r1, uint32_t& r2,
                                      uint32_t& r3, uint32_t addr) {
    asm volatile("ldmatrix.sync.aligned.m8n8.x4.shared.b16 {%0,%1,%2,%3}, [%4];"
                 : "=r"(r0), "=r"(r1), "=r"(r2), "=r"(r3) : "r"(addr));
}

__device__ __forceinline__ void mma_bf16(float* c, const uint32_t* a, const uint32_t* b) {
    asm volatile(
        "mma.sync.aligned.m16n8k16.row.col.f32.bf16.bf16.f32 "
        "{%0,%1,%2,%3}, {%4,%5,%6,%7}, {%8,%9}, {%0,%1,%2,%3};"
        : "+f"(c[0]), "+f"(c[1]), "+f"(c[2]), "+f"(c[3])
        : "r"(a[0]), "r"(a[1]), "r"(a[2]), "r"(a[3]), "r"(b[0]), "r"(b[1]));
}

__device__ __forceinline__ uint32_t pack_bf16(float a, float b) {
    bf16 h0 = __float2bfloat16(a), h1 = __float2bfloat16(b);
    return ((uint32_t)__bfloat16_as_ushort(h1) << 16) | __bfloat16_as_ushort(h0);
}

// Swizzled smem byte offset within one tile (rows of 64B = 4 chunks of 16B)
__device__ __forceinline__ uint32_t swz(int row, int chunk) {
    return (uint32_t)(row * 64 + ((chunk ^ ((row >> 1) & 3)) << 4));
}

// ---------------------------------------------------------------------------
// bf16x3 mma.sync GEMM body, NT form: C = (Ahi+Alo)*(Bhi+Blo)^T, 3-term.
// CTA 128x128, BK=32, 8 warps (2x4), warp tile 64x32.
// 3-stage cp.async pipeline, prefetch distance 2, one sync per iteration.
// Term-major MMA ordering: consecutive MMAs hit different accumulators
// (RAW reuse distance 4 instead of 1) to keep the tensor pipe streaming.
// MODE: 0 = bf16 hi/lo output; 1 = fp32 out
// ---------------------------------------------------------------------------
#define BK 32
#define TILE_B 8192
#define STAGE_B (4 * TILE_B)
#define NSTAGE 3
#define SMEM_BYTES (NSTAGE * STAGE_B)  // 98304

template <int MODE>
__device__ __forceinline__ void gemm_body(
    const bf16* __restrict__ AhiG, const bf16* __restrict__ AloG,
    const bf16* __restrict__ BhiG, const bf16* __restrict__ BloG,
    float* __restrict__ Cf, bf16* __restrict__ ChiG, bf16* __restrict__ CloG,
    int lda, int ldb, int ldc,
    long strideA, long strideB, long strideC,
    int kTiles, int bx, int by, int bz)
{
    extern __shared__ char smem[];
    const uint32_t sbase = smem_u32(smem);
    const int tid = threadIdx.x;
    const int wid = tid >> 5;
    const int lid = tid & 31;
    const int warp_m = wid >> 2;
    const int warp_n = wid & 3;
    const int g  = lid >> 2;
    const int t4 = lid & 3;

    const long aoff = (long)bz * strideA + (long)by * 128 * lda;
    const long boff = (long)bz * strideB + (long)bx * 128 * ldb;
    const bf16* Ahi = AhiG + aoff;
    const bf16* Alo = AloG + aoff;
    const bf16* Bhi = BhiG + boff;
    const bf16* Blo = BloG + boff;

    auto tbase = [&](int s, int o) { return sbase + (uint32_t)(s * STAGE_B + o * TILE_B); };

    auto load_op = [&](const bf16* G, int ld, uint32_t dst, int kt) {
        const bf16* src = G + kt * BK;
        #pragma unroll
        for (int i = 0; i < 2; i++) {
            int id  = i * 256 + tid;
            int row = id >> 2;
            int c   = id & 3;
            cp_async16(dst + swz(row, c), src + (long)row * ld + c * 8);
        }
    };
    auto load_stage = [&](int s, int kt) {
        load_op(Ahi, lda, tbase(s, 0), kt);
        load_op(Alo, lda, tbase(s, 1), kt);
        load_op(Bhi, ldb, tbase(s, 2), kt);
        load_op(Blo, ldb, tbase(s, 3), kt);
    };

    float acc[4][4][4];
    #pragma unroll
    for (int i = 0; i < 4; i++)
        #pragma unroll
        for (int j = 0; j < 4; j++)
            #pragma unroll
            for (int r = 0; r < 4; r++) acc[i][j][r] = 0.0f;

    const int mat = lid >> 3;
    const int mrw = lid & 7;
    const int a_roff = (mat & 1) * 8 + mrw;
    const int a_coff = mat >> 1;
    const int b_roff = (mat >> 1) * 8 + mrw;
    const int b_coff = mat & 1;

    load_stage(0, 0);
    CP_COMMIT();
    load_stage(1, 1);   // kTiles >= 4 always
    CP_COMMIT();

    int buf = 0;
    for (int kt = 0; kt < kTiles; kt++) {
        if (kt + 1 < kTiles) { CP_WAIT(1); } else { CP_WAIT(0); }
        __syncthreads();

        const uint32_t tAhi = tbase(buf, 0), tAlo = tbase(buf, 1);
        const uint32_t tBhi = tbase(buf, 2), tBlo = tbase(buf, 3);

        #pragma unroll
        for (int kk = 0; kk < 2; kk++) {
            uint32_t bh[4][2], bl[4][2];
            #pragma unroll
            for (int p = 0; p < 2; p++) {
                const int nb = warp_n * 32 + p * 16 + b_roff;
                const uint32_t off = swz(nb, kk * 2 + b_coff);
                ldsm4(bh[2*p][0], bh[2*p][1], bh[2*p+1][0], bh[2*p+1][1], tBhi + off);
                ldsm4(bl[2*p][0], bl[2*p][1], bl[2*p+1][0], bl[2*p+1][1], tBlo + off);
            }
            #pragma unroll
            for (int mt = 0; mt < 4; mt++) {
                const int rb = warp_m * 64 + mt * 16 + a_roff;
                const uint32_t off = swz(rb, kk * 2 + a_coff);
                uint32_t ah[4], al[4];
                ldsm4(ah[0], ah[1], ah[2], ah[3], tAhi + off);
                ldsm4(al[0], al[1], al[2], al[3], tAlo + off);
                // Term-major: consecutive MMAs use distinct accumulators.
                #pragma unroll
                for (int nt = 0; nt < 4; nt++) mma_bf16(acc[mt][nt], ah, bh[nt]);
                #pragma unroll
                for (int nt = 0; nt < 4; nt++) mma_bf16(acc[mt][nt], ah, bl[nt]);
                #pragma unroll
                for (int nt = 0; nt < 4; nt++) mma_bf16(acc[mt][nt], al, bh[nt]);
            }
        }

        if (kt + 2 < kTiles) {
            int nb = buf + 2; if (nb >= NSTAGE) nb -= NSTAGE;
            load_stage(nb, kt + 2);
            CP_COMMIT();
        }
        if (++buf == NSTAGE) buf = 0;
    }

    const long coff = (long)bz * strideC + (long)by * 128 * ldc + (long)bx * 128;
    #pragma unroll
    for (int mt = 0; mt < 4; mt++) {
        const int r0 = warp_m * 64 + mt * 16 + g;
        #pragma unroll
        for (int nt = 0; nt < 4; nt++) {
            const int c0 = warp_n * 32 + nt * 8 + 2 * t4;
            float v0 = acc[mt][nt][0], v1 = acc[mt][nt][1];
            float v2 = acc[mt][nt][2], v3 = acc[mt][nt][3];
            if (MODE == 0) {
                bf16* Chi = ChiG + coff;
                bf16* Clo = CloG + coff;
                uint32_t h01 = pack_bf16(v0, v1);
                uint32_t h23 = pack_bf16(v2, v3);
                *(uint32_t*)(Chi + (long)r0 * ldc + c0) = h01;
                *(uint32_t*)(Chi + (long)(r0 + 8) * ldc + c0) = h23;
                bf16 h0 = __ushort_as_bfloat16((uint16_t)(h01 & 0xffff));
                bf16 h1 = __ushort_as_bfloat16((uint16_t)(h01 >> 16));
                bf16 h2 = __ushort_as_bfloat16((uint16_t)(h23 & 0xffff));
                bf16 h3 = __ushort_as_bfloat16((uint16_t)(h23 >> 16));
                *(uint32_t*)(Clo + (long)r0 * ldc + c0) =
                    pack_bf16(v0 - __bfloat162float(h0), v1 - __bfloat162float(h1));
                *(uint32_t*)(Clo + (long)(r0 + 8) * ldc + c0) =
                    pack_bf16(v2 - __bfloat162float(h2), v3 - __bfloat162float(h3));
            } else {
                float* C = Cf + coff;
                *(float2*)(C + (long)r0 * ldc + c0) = make_float2(v0, v1);
                *(float2*)(C + (long)(r0 + 8) * ldc + c0) = make_float2(v2, v3);
            }
        }
    }
}

// ---------------------------------------------------------------------------
// Fused QKV projection: grid (DIM/128, BS/128, 3); z selects weight/output.
// ---------------------------------------------------------------------------
struct QKVParams {
    const bf16* bh[3]; const bf16* bl[3];
    bf16* ch[3]; bf16* cl[3];
};

__global__ __launch_bounds__(256, 2) void mma_qkv(
    const bf16* __restrict__ xhi, const bf16* __restrict__ xlo, QKVParams p)
{
    const int z = blockIdx.z;
    gemm_body<0>(xhi, xlo, p.bh[z], p.bl[z], nullptr, p.ch[z], p.cl[z],
                 DIM, DIM, DIM, 0, 0, 0, DIM / BK,
                 blockIdx.x, blockIdx.y, 0);
}

// ---------------------------------------------------------------------------
// Scores: compact triangular grid (136 blocks per batch), grid (136, BATCH).
// ---------------------------------------------------------------------------
__global__ __launch_bounds__(256, 2) void mma_scores(
    const bf16* __restrict__ Qhi, const bf16* __restrict__ Qlo,
    const bf16* __restrict__ Khi, const bf16* __restrict__ Klo,
    float* __restrict__ S)
{
    const int idx = blockIdx.x;
    int by = (int)((__fsqrt_rn(8.0f * idx + 1.0f) - 1.0f) * 0.5f);
    if ((by + 1) * (by + 2) / 2 <= idx) by++;
    if (by * (by + 1) / 2 > idx) by--;
    const int bx = idx - by * (by + 1) / 2;
    gemm_body<1>(Qhi, Qlo, Khi, Klo, S, nullptr, nullptr,
                 DIM, DIM, SEQ,
                 (long)SEQ * DIM, (long)SEQ * DIM, (long)SEQ * SEQ,
                 DIM / BK, bx, by, blockIdx.y);
}

// ---------------------------------------------------------------------------
// PV: heavy-first scheduling (by reversed), causal k-limit.
// ---------------------------------------------------------------------------
__global__ __launch_bounds__(256, 2) void mma_pv(
    const bf16* __restrict__ Phi, const bf16* __restrict__ Plo,
    const bf16* __restrict__ VThi, const bf16* __restrict__ VTlo,
    float* __restrict__ out)
{
    const int by = (int)gridDim.y - 1 - (int)blockIdx.y;   // heavy CTAs first
    gemm_body<1>(Phi, Plo, VThi, VTlo, out, nullptr, nullptr,
                 SEQ, SEQ, DIM,
                 (long)SEQ * SEQ, (long)SEQ * DIM, (long)SEQ * DIM,
                 (by + 1) * 4, blockIdx.x, by, blockIdx.z);
}

// ---------------------------------------------------------------------------
// Fused split: x + Wq + Wk + Wv in one launch.
// ---------------------------------------------------------------------------
#define NX (BATCH * SEQ * DIM)
#define NW (DIM * DIM)

struct SplitParams {
    const float* src[4];
    bf16* hi[4]; bf16* lo[4];
    int n[4];
};

__global__ __launch_bounds__(256) void split_all_kernel(SplitParams p)
{
    int i = blockIdx.x * 256 + threadIdx.x;
    #pragma unroll
    for (int s = 0; s < 4; s++) {
        int j = i;
        if (j < p.n[s]) {
            float v = p.src[s][j];
            bf16 h = __float2bfloat16(v);
            p.hi[s][j] = h;
            p.lo[s][j] = __float2bfloat16(v - __bfloat162float(h));
        }
        i -= p.n[s];
        if (i < 0) return;
    }
}

// ---------------------------------------------------------------------------
// bf16 hi/lo transpose: per batch [S, D] -> [D, S]
// ---------------------------------------------------------------------------
__global__ __launch_bounds__(256) void transpose_bf16_kernel(
    const bf16* __restrict__ hi, const bf16* __restrict__ lo,
    bf16* __restrict__ thi, bf16* __restrict__ tlo)
{
    __shared__ bf16 th[32][34], tl[32][34];
    const int b = blockIdx.z;
    const int s0 = blockIdx.x * 32, d0 = blockIdx.y * 32;
    const bf16* srch = hi + (long)b * SEQ * DIM;
    const bf16* srcl = lo + (long)b * SEQ * DIM;
    bf16* dsth = thi + (long)b * SEQ * DIM;
    bf16* dstl = tlo + (long)b * SEQ * DIM;
    const int x = threadIdx.x, y = threadIdx.y;
    #pragma unroll
    for (int i = 0; i < 32; i += 8) {
        long o = (long)(s0 + y + i) * DIM + d0 + x;
        th[y + i][x] = srch[o];
        tl[y + i][x] = srcl[o];
    }
    __syncthreads();
    #pragma unroll
    for (int i = 0; i < 32; i += 8) {
        long o = (long)(d0 + y + i) * SEQ + s0 + x;
        dsth[o] = th[x][y + i];
        dstl[o] = tl[x][y + i];
    }
}

// ---------------------------------------------------------------------------
// Causal row softmax, single pass: row held in registers (<=8 elems/thread).
// ---------------------------------------------------------------------------
__global__ __launch_bounds__(256) void softmax_kernel(
    const float* __restrict__ S, bf16* __restrict__ Phi, bf16* __restrict__ Plo)
{
    const int q = blockIdx.x;
    const int b = blockIdx.y;
    const float* row = S + (long)b * SEQ * SEQ + (long)q * SEQ;
    bf16* ph = Phi + (long)b * SEQ * SEQ + (long)q * SEQ;
    bf16* pl = Plo + (long)b * SEQ * SEQ + (long)q * SEQ;
    const int klen = q + 1;
    const int kpad = ((q >> 7) + 1) << 7;
    const int tid = threadIdx.x;
    const float scale = 0.03125f;   // 1/sqrt(1024)

    __shared__ float red[8];

    float v[8];
    float m = -1e30f;
    #pragma unroll
    for (int i = 0; i < 8; i++) {
        int j = tid + i * 256;
        v[i] = (j < klen) ? row[j] * scale : -1e30f;
        m = fmaxf(m, v[i]);
    }
    #pragma unroll
    for (int o = 16; o > 0; o >>= 1) m = fmaxf(m, __shfl_xor_sync(0xffffffffu, m, o));
    if ((tid & 31) == 0) red[tid >> 5] = m;
    __syncthreads();
    if (tid < 32) {
        float t = (tid < 8) ? red[tid] : -1e30f;
        #pragma unroll
        for (int o = 4; o > 0; o >>= 1) t = fmaxf(t, __shfl_xor_sync(0xffffffffu, t, o));
        if (tid == 0) red[0] = t;
    }
    __syncthreads();
    m = red[0];
    __syncthreads();

    float s = 0.0f;
    #pragma unroll
    for (int i = 0; i < 8; i++) {
        v[i] = __expf(v[i] - m);
        s += v[i];
    }
    #pragma unroll
    for (int o = 16; o > 0; o >>= 1) s += __shfl_xor_sync(0xffffffffu, s, o);
    if ((tid & 31) == 0) red[tid >> 5] = s;
    __syncthreads();
    if (tid < 32) {
        float t = (tid < 8) ? red[tid] : 0.0f;
        #pragma unroll
        for (int o = 4; o > 0; o >>= 1) t += __shfl_xor_sync(0xffffffffu, t, o);
        if (tid == 0) red[0] = t;
    }
    __syncthreads();
    const float inv = 1.0f / red[0];

    #pragma unroll
    for (int i = 0; i < 8; i++) {
        int j = tid + i * 256;
        if (j < klen) {
            float p = v[i] * inv;
            bf16 h = __float2bfloat16(p);
            ph[j] = h;
            pl[j] = __float2bfloat16(p - __bfloat162float(h));
        } else if (j < kpad) {
            ph[j] = __float2bfloat16(0.0f);
            pl[j] = __float2bfloat16(0.0f);
        }
    }
}

// ---------------------------------------------------------------------------
extern "C" void kernel_launch(void* const* d_in, const int* in_sizes, int n_in,
                              void* d_out, int out_size)
{
    const float* x  = (const float*)d_in[0];
    const float* Wq = (const float*)d_in[1];
    const float* Wk = (const float*)d_in[2];
    const float* Wv = (const float*)d_in[3];
    float* out = (float*)d_out;

    bf16 *xhi, *xlo, *Wqhi, *Wqlo, *Wkhi, *Wklo, *Wvhi, *Wvlo;
    bf16 *Qhi, *Qlo, *Khi, *Klo, *Vhi, *Vlo, *VThi, *VTlo, *Phi, *Plo;
    float *S;
    cudaGetSymbolAddress((void**)&xhi,  g_xhi);  cudaGetSymbolAddress((void**)&xlo,  g_xlo);
    cudaGetSymbolAddress((void**)&Wqhi, g_Wqhi); cudaGetSymbolAddress((void**)&Wqlo, g_Wqlo);
    cudaGetSymbolAddress((void**)&Wkhi, g_Wkhi); cudaGetSymbolAddress((void**)&Wklo, g_Wklo);
    cudaGetSymbolAddress((void**)&Wvhi, g_Wvhi); cudaGetSymbolAddress((void**)&Wvlo, g_Wvlo);
    cudaGetSymbolAddress((void**)&Qhi,  g_Qhi);  cudaGetSymbolAddress((void**)&Qlo,  g_Qlo);
    cudaGetSymbolAddress((void**)&Khi,  g_Khi);  cudaGetSymbolAddress((void**)&Klo,  g_Klo);
    cudaGetSymbolAddress((void**)&Vhi,  g_Vhi);  cudaGetSymbolAddress((void**)&Vlo,  g_Vlo);
    cudaGetSymbolAddress((void**)&VThi, g_VThi); cudaGetSymbolAddress((void**)&VTlo, g_VTlo);
    cudaGetSymbolAddress((void**)&S,    g_S);
    cudaGetSymbolAddress((void**)&Phi,  g_Phi);  cudaGetSymbolAddress((void**)&Plo,  g_Plo);

    cudaFuncSetAttribute(mma_qkv,    cudaFuncAttributeMaxDynamicSharedMemorySize, SMEM_BYTES);
    cudaFuncSetAttribute(mma_scores, cudaFuncAttributeMaxDynamicSharedMemorySize, SMEM_BYTES);
    cudaFuncSetAttribute(mma_pv,     cudaFuncAttributeMaxDynamicSharedMemorySize, SMEM_BYTES);

    // 0) fused splits (x, Wq, Wk, Wv)
    {
        SplitParams sp;
        sp.src[0] = x;  sp.hi[0] = xhi;  sp.lo[0] = xlo;  sp.n[0] = NX;
        sp.src[1] = Wq; sp.hi[1] = Wqhi; sp.lo[1] = Wqlo; sp.n[1] = NW;
        sp.src[2] = Wk; sp.hi[2] = Wkhi; sp.lo[2] = Wklo; sp.n[2] = NW;
        sp.src[3] = Wv; sp.hi[3] = Wvhi; sp.lo[3] = Wvlo; sp.n[3] = NW;
        int total = NX + 3 * NW;
        split_all_kernel<<<(total + 255) / 256, 256>>>(sp);
    }

    // 1) fused QKV projections (one launch, 1536 CTAs)
    {
        QKVParams p;
        p.bh[0] = Wqhi; p.bl[0] = Wqlo; p.ch[0] = Qhi; p.cl[0] = Qlo;
        p.bh[1] = Wkhi; p.bl[1] = Wklo; p.ch[1] = Khi; p.cl[1] = Klo;
        p.bh[2] = Wvhi; p.bl[2] = Wvlo; p.ch[2] = Vhi; p.cl[2] = Vlo;
        dim3 grid(DIM / 128, (BATCH * SEQ) / 128, 3);
        mma_qkv<<<grid, 256, SMEM_BYTES>>>(xhi, xlo, p);
    }

    // 2) V transpose (bf16 permutation)
    {
        dim3 grid(SEQ / 32, DIM / 32, BATCH);
        transpose_bf16_kernel<<<grid, dim3(32, 8)>>>(Vhi, Vlo, VThi, VTlo);
    }

    // 3) scores: compact triangular grid (136 blocks x 4 batches)
    {
        dim3 grid(136, BATCH);
        mma_scores<<<grid, 256, SMEM_BYTES>>>(Qhi, Qlo, Khi, Klo, S);
    }

    // 4) softmax -> P hi/lo
    {
        dim3 grid(SEQ, BATCH);
        softmax_kernel<<<grid, 256>>>(S, Phi, Plo);
    }

    // 5) O = P @ VT^T, heavy-first scheduling
    {
        dim3 grid(DIM / 128, SEQ / 128, BATCH);
        mma_pv<<<grid, 256, SMEM_BYTES>>>(Phi, Plo, VThi, VTlo, out);
    }
}

// round 17
// speedup vs baseline: 1.4403x; 1.0389x over previous
#include <cuda_runtime.h>
#include <cuda_bf16.h>
#include <cstdint>
#include <math.h>

#define BATCH 4
#define SEQ   2048
#define DIM   1024

typedef __nv_bfloat16 bf16;

// Scratch (static device allocations; allowed)
__device__ bf16  g_xhi[BATCH * SEQ * DIM], g_xlo[BATCH * SEQ * DIM];
__device__ bf16  g_Wqhi[DIM * DIM], g_Wqlo[DIM * DIM];
__device__ bf16  g_Wkhi[DIM * DIM], g_Wklo[DIM * DIM];
__device__ bf16  g_Wvhi[DIM * DIM], g_Wvlo[DIM * DIM];
__device__ bf16  g_Qhi[BATCH * SEQ * DIM], g_Qlo[BATCH * SEQ * DIM];
__device__ bf16  g_Khi[BATCH * SEQ * DIM], g_Klo[BATCH * SEQ * DIM];
__device__ bf16  g_Vhi[BATCH * SEQ * DIM], g_Vlo[BATCH * SEQ * DIM];
__device__ bf16  g_VThi[BATCH * SEQ * DIM], g_VTlo[BATCH * SEQ * DIM];
__device__ float g_S[(size_t)BATCH * SEQ * SEQ];
__device__ bf16  g_Phi[(size_t)BATCH * SEQ * SEQ], g_Plo[(size_t)BATCH * SEQ * SEQ];

// ---------------------------------------------------------------------------
__device__ __forceinline__ uint32_t smem_u32(const void* p) {
    uint32_t a;
    asm("{ .reg .u64 t; cvta.to.shared.u64 t, %1; cvt.u32.u64 %0, t; }"
        : "=r"(a) : "l"(p));
    return a;
}
__device__ __forceinline__ void cp_async16(uint32_t dst, const void* src) {
    asm volatile("cp.async.cg.shared.global [%0], [%1], 16;"
                 :: "r"(dst), "l"(src) : "memory");
}
#define CP_COMMIT() asm volatile("cp.async.commit_group;" ::: "memory")
#define CP_WAIT(N)  asm volatile("cp.async.wait_group %0;" :: "n"(N) : "memory")

__device__ __forceinline__ void ldsm4(uint32_t& r0, uint32_t& r1, uint32_t& r2,
                                      uint32_t& r3, uint32_t addr) {
    asm volatile("ldmatrix.sync.aligned.m8n8.x4.shared.b16 {%0,%1,%2,%3}, [%4];"
                 : "=r"(r0), "=r"(r1), "=r"(r2), "=r"(r3) : "r"(addr));
}

__device__ __forceinline__ void mma_bf16(float* c, const uint32_t* a, const uint32_t* b) {
    asm volatile(
        "mma.sync.aligned.m16n8k16.row.col.f32.bf16.bf16.f32 "
        "{%0,%1,%2,%3}, {%4,%5,%6,%7}, {%8,%9}, {%0,%1,%2,%3};"
        : "+f"(c[0]), "+f"(c[1]), "+f"(c[2]), "+f"(c[3])
        : "r"(a[0]), "r"(a[1]), "r"(a[2]), "r"(a[3]), "r"(b[0]), "r"(b[1]));
}

__device__ __forceinline__ uint32_t pack_bf16(float a, float b) {
    bf16 h0 = __float2bfloat16(a), h1 = __float2bfloat16(b);
    return ((uint32_t)__bfloat16_as_ushort(h1) << 16) | __bfloat16_as_ushort(h0);
}

// Swizzled smem byte offset within one tile (rows of 64B = 4 chunks of 16B)
__device__ __forceinline__ uint32_t swz(int row, int chunk) {
    return (uint32_t)(row * 64 + ((chunk ^ ((row >> 1) & 3)) << 4));
}

// ---------------------------------------------------------------------------
// bf16x3 mma.sync GEMM body, NT form: C = (Ahi+Alo)*(Bhi+Blo)^T, 3-term.
// CTA 128x128, BK=32, 8 warps (2x4), warp tile 64x32.
// 3-stage cp.async pipeline, prefetch distance 2, one sync per iteration.
// MODE: 0 = bf16 hi/lo output; 1 = fp32 out
// ---------------------------------------------------------------------------
#define BK 32
#define TILE_B 8192
#define STAGE_B (4 * TILE_B)
#define NSTAGE 3
#define SMEM_BYTES (NSTAGE * STAGE_B)  // 98304

template <int MODE>
__device__ __forceinline__ void gemm_body(
    const bf16* __restrict__ AhiG, const bf16* __restrict__ AloG,
    const bf16* __restrict__ BhiG, const bf16* __restrict__ BloG,
    float* __restrict__ Cf, bf16* __restrict__ ChiG, bf16* __restrict__ CloG,
    int lda, int ldb, int ldc,
    long strideA, long strideB, long strideC,
    int kTiles, int bx, int by, int bz)
{
    extern __shared__ char smem[];
    const uint32_t sbase = smem_u32(smem);
    const int tid = threadIdx.x;
    const int wid = tid >> 5;
    const int lid = tid & 31;
    const int warp_m = wid >> 2;
    const int warp_n = wid & 3;
    const int g  = lid >> 2;
    const int t4 = lid & 3;

    const long aoff = (long)bz * strideA + (long)by * 128 * lda;
    const long boff = (long)bz * strideB + (long)bx * 128 * ldb;
    const bf16* Ahi = AhiG + aoff;
    const bf16* Alo = AloG + aoff;
    const bf16* Bhi = BhiG + boff;
    const bf16* Blo = BloG + boff;

    auto tbase = [&](int s, int o) { return sbase + (uint32_t)(s * STAGE_B + o * TILE_B); };

    auto load_op = [&](const bf16* G, int ld, uint32_t dst, int kt) {
        const bf16* src = G + kt * BK;
        #pragma unroll
        for (int i = 0; i < 2; i++) {
            int id  = i * 256 + tid;
            int row = id >> 2;
            int c   = id & 3;
            cp_async16(dst + swz(row, c), src + (long)row * ld + c * 8);
        }
    };
    auto load_stage = [&](int s, int kt) {
        load_op(Ahi, lda, tbase(s, 0), kt);
        load_op(Alo, lda, tbase(s, 1), kt);
        load_op(Bhi, ldb, tbase(s, 2), kt);
        load_op(Blo, ldb, tbase(s, 3), kt);
    };

    float acc[4][4][4];
    #pragma unroll
    for (int i = 0; i < 4; i++)
        #pragma unroll
        for (int j = 0; j < 4; j++)
            #pragma unroll
            for (int r = 0; r < 4; r++) acc[i][j][r] = 0.0f;

    const int mat = lid >> 3;
    const int mrw = lid & 7;
    const int a_roff = (mat & 1) * 8 + mrw;
    const int a_coff = mat >> 1;
    const int b_roff = (mat >> 1) * 8 + mrw;
    const int b_coff = mat & 1;

    load_stage(0, 0);
    CP_COMMIT();
    load_stage(1, 1);   // kTiles >= 4 always
    CP_COMMIT();

    int buf = 0;
    for (int kt = 0; kt < kTiles; kt++) {
        if (kt + 1 < kTiles) { CP_WAIT(1); } else { CP_WAIT(0); }
        __syncthreads();

        const uint32_t tAhi = tbase(buf, 0), tAlo = tbase(buf, 1);
        const uint32_t tBhi = tbase(buf, 2), tBlo = tbase(buf, 3);

        #pragma unroll
        for (int kk = 0; kk < 2; kk++) {
            uint32_t bh[4][2], bl[4][2];
            #pragma unroll
            for (int p = 0; p < 2; p++) {
                const int nb = warp_n * 32 + p * 16 + b_roff;
                const uint32_t off = swz(nb, kk * 2 + b_coff);
                ldsm4(bh[2*p][0], bh[2*p][1], bh[2*p+1][0], bh[2*p+1][1], tBhi + off);
                ldsm4(bl[2*p][0], bl[2*p][1], bl[2*p+1][0], bl[2*p+1][1], tBlo + off);
            }
            #pragma unroll
            for (int mt = 0; mt < 4; mt++) {
                const int rb = warp_m * 64 + mt * 16 + a_roff;
                const uint32_t off = swz(rb, kk * 2 + a_coff);
                uint32_t ah[4], al[4];
                ldsm4(ah[0], ah[1], ah[2], ah[3], tAhi + off);
                ldsm4(al[0], al[1], al[2], al[3], tAlo + off);
                #pragma unroll
                for (int nt = 0; nt < 4; nt++) {
                    mma_bf16(acc[mt][nt], ah, bh[nt]);
                    mma_bf16(acc[mt][nt], ah, bl[nt]);
                    mma_bf16(acc[mt][nt], al, bh[nt]);
                }
            }
        }

        if (kt + 2 < kTiles) {
            int nb = buf + 2; if (nb >= NSTAGE) nb -= NSTAGE;
            load_stage(nb, kt + 2);
            CP_COMMIT();
        }
        if (++buf == NSTAGE) buf = 0;
    }

    const long coff = (long)bz * strideC + (long)by * 128 * ldc + (long)bx * 128;
    #pragma unroll
    for (int mt = 0; mt < 4; mt++) {
        const int r0 = warp_m * 64 + mt * 16 + g;
        #pragma unroll
        for (int nt = 0; nt < 4; nt++) {
            const int c0 = warp_n * 32 + nt * 8 + 2 * t4;
            float v0 = acc[mt][nt][0], v1 = acc[mt][nt][1];
            float v2 = acc[mt][nt][2], v3 = acc[mt][nt][3];
            if (MODE == 0) {
                bf16* Chi = ChiG + coff;
                bf16* Clo = CloG + coff;
                uint32_t h01 = pack_bf16(v0, v1);
                uint32_t h23 = pack_bf16(v2, v3);
                *(uint32_t*)(Chi + (long)r0 * ldc + c0) = h01;
                *(uint32_t*)(Chi + (long)(r0 + 8) * ldc + c0) = h23;
                bf16 h0 = __ushort_as_bfloat16((uint16_t)(h01 & 0xffff));
                bf16 h1 = __ushort_as_bfloat16((uint16_t)(h01 >> 16));
                bf16 h2 = __ushort_as_bfloat16((uint16_t)(h23 & 0xffff));
                bf16 h3 = __ushort_as_bfloat16((uint16_t)(h23 >> 16));
                *(uint32_t*)(Clo + (long)r0 * ldc + c0) =
                    pack_bf16(v0 - __bfloat162float(h0), v1 - __bfloat162float(h1));
                *(uint32_t*)(Clo + (long)(r0 + 8) * ldc + c0) =
                    pack_bf16(v2 - __bfloat162float(h2), v3 - __bfloat162float(h3));
            } else {
                float* C = Cf + coff;
                *(float2*)(C + (long)r0 * ldc + c0) = make_float2(v0, v1);
                *(float2*)(C + (long)(r0 + 8) * ldc + c0) = make_float2(v2, v3);
            }
        }
    }
}

// ---------------------------------------------------------------------------
// Fused QKV projection: grid (DIM/128, BS/128, 3); z selects weight/output.
// ---------------------------------------------------------------------------
struct QKVParams {
    const bf16* bh[3]; const bf16* bl[3];
    bf16* ch[3]; bf16* cl[3];
};

__global__ __launch_bounds__(256, 2) void mma_qkv(
    const bf16* __restrict__ xhi, const bf16* __restrict__ xlo, QKVParams p)
{
    const int z = blockIdx.z;
    gemm_body<0>(xhi, xlo, p.bh[z], p.bl[z], nullptr, p.ch[z], p.cl[z],
                 DIM, DIM, DIM, 0, 0, 0, DIM / BK,
                 blockIdx.x, blockIdx.y, 0);
}

// ---------------------------------------------------------------------------
// Scores for ONE batch: compact triangular grid (136 blocks).
// ---------------------------------------------------------------------------
__global__ __launch_bounds__(256, 2) void mma_scores(
    const bf16* __restrict__ Qhi, const bf16* __restrict__ Qlo,
    const bf16* __restrict__ Khi, const bf16* __restrict__ Klo,
    float* __restrict__ S, int batch)
{
    const int idx = blockIdx.x;
    int by = (int)((__fsqrt_rn(8.0f * idx + 1.0f) - 1.0f) * 0.5f);
    if ((by + 1) * (by + 2) / 2 <= idx) by++;
    if (by * (by + 1) / 2 > idx) by--;
    const int bx = idx - by * (by + 1) / 2;
    gemm_body<1>(Qhi, Qlo, Khi, Klo, S, nullptr, nullptr,
                 DIM, DIM, SEQ,
                 (long)SEQ * DIM, (long)SEQ * DIM, (long)SEQ * SEQ,
                 DIM / BK, bx, by, batch);
}

// ---------------------------------------------------------------------------
// PV for ONE batch: heavy-first scheduling (by reversed), causal k-limit.
// ---------------------------------------------------------------------------
__global__ __launch_bounds__(256, 2) void mma_pv(
    const bf16* __restrict__ Phi, const bf16* __restrict__ Plo,
    const bf16* __restrict__ VThi, const bf16* __restrict__ VTlo,
    float* __restrict__ out, int batch)
{
    const int by = (int)gridDim.y - 1 - (int)blockIdx.y;   // heavy CTAs first
    gemm_body<1>(Phi, Plo, VThi, VTlo, out, nullptr, nullptr,
                 SEQ, SEQ, DIM,
                 (long)SEQ * SEQ, (long)SEQ * DIM, (long)SEQ * DIM,
                 (by + 1) * 4, blockIdx.x, by, batch);
}

// ---------------------------------------------------------------------------
// Fused split: x + Wq + Wk + Wv in one launch.
// ---------------------------------------------------------------------------
#define NX (BATCH * SEQ * DIM)
#define NW (DIM * DIM)

struct SplitParams {
    const float* src[4];
    bf16* hi[4]; bf16* lo[4];
    int n[4];
};

__global__ __launch_bounds__(256) void split_all_kernel(SplitParams p)
{
    int i = blockIdx.x * 256 + threadIdx.x;
    #pragma unroll
    for (int s = 0; s < 4; s++) {
        int j = i;
        if (j < p.n[s]) {
            float v = p.src[s][j];
            bf16 h = __float2bfloat16(v);
            p.hi[s][j] = h;
            p.lo[s][j] = __float2bfloat16(v - __bfloat162float(h));
        }
        i -= p.n[s];
        if (i < 0) return;
    }
}

// ---------------------------------------------------------------------------
// bf16 hi/lo transpose for ONE batch: [S, D] -> [D, S]
// ---------------------------------------------------------------------------
__global__ __launch_bounds__(256) void transpose_bf16_kernel(
    const bf16* __restrict__ hi, const bf16* __restrict__ lo,
    bf16* __restrict__ thi, bf16* __restrict__ tlo, int batch)
{
    __shared__ bf16 th[32][34], tl[32][34];
    const int s0 = blockIdx.x * 32, d0 = blockIdx.y * 32;
    const bf16* srch = hi + (long)batch * SEQ * DIM;
    const bf16* srcl = lo + (long)batch * SEQ * DIM;
    bf16* dsth = thi + (long)batch * SEQ * DIM;
    bf16* dstl = tlo + (long)batch * SEQ * DIM;
    const int x = threadIdx.x, y = threadIdx.y;
    #pragma unroll
    for (int i = 0; i < 32; i += 8) {
        long o = (long)(s0 + y + i) * DIM + d0 + x;
        th[y + i][x] = srch[o];
        tl[y + i][x] = srcl[o];
    }
    __syncthreads();
    #pragma unroll
    for (int i = 0; i < 32; i += 8) {
        long o = (long)(d0 + y + i) * SEQ + s0 + x;
        dsth[o] = th[x][y + i];
        dstl[o] = tl[x][y + i];
    }
}

// ---------------------------------------------------------------------------
// Causal row softmax for ONE batch, single pass (<=8 elems/thread).
// ---------------------------------------------------------------------------
__global__ __launch_bounds__(256) void softmax_kernel(
    const float* __restrict__ S, bf16* __restrict__ Phi, bf16* __restrict__ Plo,
    int batch)
{
    const int q = blockIdx.x;
    const float* row = S + (long)batch * SEQ * SEQ + (long)q * SEQ;
    bf16* ph = Phi + (long)batch * SEQ * SEQ + (long)q * SEQ;
    bf16* pl = Plo + (long)batch * SEQ * SEQ + (long)q * SEQ;
    const int klen = q + 1;
    const int kpad = ((q >> 7) + 1) << 7;
    const int tid = threadIdx.x;
    const float scale = 0.03125f;   // 1/sqrt(1024)

    __shared__ float red[8];

    float v[8];
    float m = -1e30f;
    #pragma unroll
    for (int i = 0; i < 8; i++) {
        int j = tid + i * 256;
        v[i] = (j < klen) ? row[j] * scale : -1e30f;
        m = fmaxf(m, v[i]);
    }
    #pragma unroll
    for (int o = 16; o > 0; o >>= 1) m = fmaxf(m, __shfl_xor_sync(0xffffffffu, m, o));
    if ((tid & 31) == 0) red[tid >> 5] = m;
    __syncthreads();
    if (tid < 32) {
        float t = (tid < 8) ? red[tid] : -1e30f;
        #pragma unroll
        for (int o = 4; o > 0; o >>= 1) t = fmaxf(t, __shfl_xor_sync(0xffffffffu, t, o));
        if (tid == 0) red[0] = t;
    }
    __syncthreads();
    m = red[0];
    __syncthreads();

    float s = 0.0f;
    #pragma unroll
    for (int i = 0; i < 8; i++) {
        v[i] = __expf(v[i] - m);
        s += v[i];
    }
    #pragma unroll
    for (int o = 16; o > 0; o >>= 1) s += __shfl_xor_sync(0xffffffffu, s, o);
    if ((tid & 31) == 0) red[tid >> 5] = s;
    __syncthreads();
    if (tid < 32) {
        float t = (tid < 8) ? red[tid] : 0.0f;
        #pragma unroll
        for (int o = 4; o > 0; o >>= 1) t += __shfl_xor_sync(0xffffffffu, t, o);
        if (tid == 0) red[0] = t;
    }
    __syncthreads();
    const float inv = 1.0f / red[0];

    #pragma unroll
    for (int i = 0; i < 8; i++) {
        int j = tid + i * 256;
        if (j < klen) {
            float p = v[i] * inv;
            bf16 h = __float2bfloat16(p);
            ph[j] = h;
            pl[j] = __float2bfloat16(p - __bfloat162float(h));
        } else if (j < kpad) {
            ph[j] = __float2bfloat16(0.0f);
            pl[j] = __float2bfloat16(0.0f);
        }
    }
}

// ---------------------------------------------------------------------------
extern "C" void kernel_launch(void* const* d_in, const int* in_sizes, int n_in,
                              void* d_out, int out_size)
{
    const float* x  = (const float*)d_in[0];
    const float* Wq = (const float*)d_in[1];
    const float* Wk = (const float*)d_in[2];
    const float* Wv = (const float*)d_in[3];
    float* out = (float*)d_out;

    bf16 *xhi, *xlo, *Wqhi, *Wqlo, *Wkhi, *Wklo, *Wvhi, *Wvlo;
    bf16 *Qhi, *Qlo, *Khi, *Klo, *Vhi, *Vlo, *VThi, *VTlo, *Phi, *Plo;
    float *S;
    cudaGetSymbolAddress((void**)&xhi,  g_xhi);  cudaGetSymbolAddress((void**)&xlo,  g_xlo);
    cudaGetSymbolAddress((void**)&Wqhi, g_Wqhi); cudaGetSymbolAddress((void**)&Wqlo, g_Wqlo);
    cudaGetSymbolAddress((void**)&Wkhi, g_Wkhi); cudaGetSymbolAddress((void**)&Wklo, g_Wklo);
    cudaGetSymbolAddress((void**)&Wvhi, g_Wvhi); cudaGetSymbolAddress((void**)&Wvlo, g_Wvlo);
    cudaGetSymbolAddress((void**)&Qhi,  g_Qhi);  cudaGetSymbolAddress((void**)&Qlo,  g_Qlo);
    cudaGetSymbolAddress((void**)&Khi,  g_Khi);  cudaGetSymbolAddress((void**)&Klo,  g_Klo);
    cudaGetSymbolAddress((void**)&Vhi,  g_Vhi);  cudaGetSymbolAddress((void**)&Vlo,  g_Vlo);
    cudaGetSymbolAddress((void**)&VThi, g_VThi); cudaGetSymbolAddress((void**)&VTlo, g_VTlo);
    cudaGetSymbolAddress((void**)&S,    g_S);
    cudaGetSymbolAddress((void**)&Phi,  g_Phi);  cudaGetSymbolAddress((void**)&Plo,  g_Plo);

    cudaFuncSetAttribute(mma_qkv,    cudaFuncAttributeMaxDynamicSharedMemorySize, SMEM_BYTES);
    cudaFuncSetAttribute(mma_scores, cudaFuncAttributeMaxDynamicSharedMemorySize, SMEM_BYTES);
    cudaFuncSetAttribute(mma_pv,     cudaFuncAttributeMaxDynamicSharedMemorySize, SMEM_BYTES);

    // Per-batch streams + fork/join events (created at capture time; replay
    // cost is zero — the graph holds the dependency edges, not the streams).
    cudaStream_t bs[BATCH];
    cudaEvent_t ev_qkv, ev_b[BATCH];
    for (int b = 0; b < BATCH; b++)
        cudaStreamCreateWithFlags(&bs[b], cudaStreamNonBlocking);
    cudaEventCreateWithFlags(&ev_qkv, cudaEventDisableTiming);
    for (int b = 0; b < BATCH; b++)
        cudaEventCreateWithFlags(&ev_b[b], cudaEventDisableTiming);

    // 0) fused splits (x, Wq, Wk, Wv) — legacy stream
    {
        SplitParams sp;
        sp.src[0] = x;  sp.hi[0] = xhi;  sp.lo[0] = xlo;  sp.n[0] = NX;
        sp.src[1] = Wq; sp.hi[1] = Wqhi; sp.lo[1] = Wqlo; sp.n[1] = NW;
        sp.src[2] = Wk; sp.hi[2] = Wkhi; sp.lo[2] = Wklo; sp.n[2] = NW;
        sp.src[3] = Wv; sp.hi[3] = Wvhi; sp.lo[3] = Wvlo; sp.n[3] = NW;
        int total = NX + 3 * NW;
        split_all_kernel<<<(total + 255) / 256, 256>>>(sp);
    }

    // 1) fused QKV projections — legacy stream
    {
        QKVParams p;
        p.bh[0] = Wqhi; p.bl[0] = Wqlo; p.ch[0] = Qhi; p.cl[0] = Qlo;
        p.bh[1] = Wkhi; p.bl[1] = Wklo; p.ch[1] = Khi; p.cl[1] = Klo;
        p.bh[2] = Wvhi; p.bl[2] = Wvlo; p.ch[2] = Vhi; p.cl[2] = Vlo;
        dim3 grid(DIM / 128, (BATCH * SEQ) / 128, 3);
        mma_qkv<<<grid, 256, SMEM_BYTES>>>(xhi, xlo, p);
    }
    cudaEventRecord(ev_qkv, 0);

    // 2) Per-batch pipelines: transpose -> scores -> softmax -> PV
    for (int b = 0; b < BATCH; b++) {
        cudaStreamWaitEvent(bs[b], ev_qkv, 0);
        {
            dim3 grid(SEQ / 32, DIM / 32);
            transpose_bf16_kernel<<<grid, dim3(32, 8), 0, bs[b]>>>(
                Vhi, Vlo, VThi, VTlo, b);
        }
        mma_scores<<<136, 256, SMEM_BYTES, bs[b]>>>(Qhi, Qlo, Khi, Klo, S, b);
        softmax_kernel<<<SEQ, 256, 0, bs[b]>>>(S, Phi, Plo, b);
        {
            dim3 grid(DIM / 128, SEQ / 128);
            mma_pv<<<grid, 256, SMEM_BYTES, bs[b]>>>(Phi, Plo, VThi, VTlo, out, b);
        }
        cudaEventRecord(ev_b[b], bs[b]);
    }

    // 3) Join all batch streams back into the legacy stream
    for (int b = 0; b < BATCH; b++)
        cudaStreamWaitEvent(0, ev_b[b], 0);

    for (int b = 0; b < BATCH; b++) cudaStreamDestroy(bs[b]);
    cudaEventDestroy(ev_qkv);
    for (int b = 0; b < BATCH; b++) cudaEventDestroy(ev_b[b]);
}